// round 5
// baseline (speedup 1.0000x reference)
#include <cuda_runtime.h>
#include <cuda_bf16.h>

#define BATCH 16384
#define DIM   1024
#define DIM4  (DIM / 4)       // 256 float4 per row
#define NL    4

#define TPB 256
#define WARPS_PER_CTA 8
#define ROWS_PER_CTA (WARPS_PER_CTA * 2)   // 16 (2 rows per warp)
#define GRID (BATCH / ROWS_PER_CTA)        // 1024

__device__ __forceinline__ float dot4(float4 x, float4 w, float acc) {
    return fmaf(x.x, w.x, fmaf(x.y, w.y, fmaf(x.z, w.z, fmaf(x.w, w.w, acc))));
}

// ---------------------------------------------------------------------------
// Single fused kernel.
//   Step 1: issue ALL x0 loads (__ldcs, pure DRAM-miss stream) into registers.
//   Step 2: while misses are in flight, load W+b (L2-hot), build sW/sC in
//           shared, block-reduce D_l = dot(c_l, W_l). Hidden under latency.
//   Step 3: dot products vs smem W, shuffle-reduce, scalar recurrence.
//   Step 4: out = a*x0 + Csum, streaming stores.
// ---------------------------------------------------------------------------
__global__ __launch_bounds__(TPB) void crossnet_fused(
    const float4* __restrict__ x0,
    const float4* __restrict__ W4,
    const float4* __restrict__ b4,
    float4* __restrict__ out)
{
    __shared__ float4 sW[NL][DIM4];   // 16 KB
    __shared__ float4 sC[DIM4];       //  4 KB
    __shared__ float  s_red[3][WARPS_PER_CTA];
    __shared__ float  sD[NL];

    const int tid  = threadIdx.x;
    const int warp = tid >> 5;
    const int lane = tid & 31;

    const int rowA = (blockIdx.x * WARPS_PER_CTA + warp) * 2;
    const float4* __restrict__ xa = x0 + (size_t)rowA * DIM4;
    const float4* __restrict__ xb = xa + DIM4;

    // ---- Step 1: front-batch all 16 x0 loads per warp (DRAM misses) ----
    float4 xA[8], xB[8];
    #pragma unroll
    for (int k = 0; k < 8; k++) {
        const int i = k * 32 + lane;
        xA[k] = __ldcs(&xa[i]);
        xB[k] = __ldcs(&xb[i]);
    }

    // ---- Step 2: CTA-local precompute, hidden under the misses ----
    // 256 threads x 1 float4 column-chunk == DIM4 entries.
    {
        float4 w0 = W4[tid];
        float4 w1 = W4[DIM4 + tid];
        float4 w2 = W4[2 * DIM4 + tid];
        float4 w3 = W4[3 * DIM4 + tid];
        float4 bb0 = b4[tid];
        float4 bb1 = b4[DIM4 + tid];
        float4 bb2 = b4[2 * DIM4 + tid];
        float4 bb3 = b4[3 * DIM4 + tid];

        sW[0][tid] = w0;
        sW[1][tid] = w1;
        sW[2][tid] = w2;
        sW[3][tid] = w3;

        float4 c1, c2, c3, c4;
        c1.x = bb0.x;        c1.y = bb0.y;        c1.z = bb0.z;        c1.w = bb0.w;
        c2.x = c1.x + bb1.x; c2.y = c1.y + bb1.y; c2.z = c1.z + bb1.z; c2.w = c1.w + bb1.w;
        c3.x = c2.x + bb2.x; c3.y = c2.y + bb2.y; c3.z = c2.z + bb2.z; c3.w = c2.w + bb2.w;
        c4.x = c3.x + bb3.x; c4.y = c3.y + bb3.y; c4.z = c3.z + bb3.z; c4.w = c3.w + bb3.w;
        sC[tid] = c4;

        float p1 = dot4(c1, w1, 0.f);
        float p2 = dot4(c2, w2, 0.f);
        float p3 = dot4(c3, w3, 0.f);

        #pragma unroll
        for (int o = 16; o; o >>= 1) {
            p1 += __shfl_xor_sync(0xFFFFFFFFu, p1, o);
            p2 += __shfl_xor_sync(0xFFFFFFFFu, p2, o);
            p3 += __shfl_xor_sync(0xFFFFFFFFu, p3, o);
        }
        if (lane == 0) {
            s_red[0][warp] = p1;
            s_red[1][warp] = p2;
            s_red[2][warp] = p3;
        }
    }
    __syncthreads();   // sW, sC, s_red visible

    if (warp == 0 && lane < WARPS_PER_CTA) {
        float q1 = s_red[0][lane];
        float q2 = s_red[1][lane];
        float q3 = s_red[2][lane];
        #pragma unroll
        for (int o = 4; o; o >>= 1) {
            q1 += __shfl_xor_sync(0xFFu, q1, o);
            q2 += __shfl_xor_sync(0xFFu, q2, o);
            q3 += __shfl_xor_sync(0xFFu, q3, o);
        }
        if (lane == 0) { sD[1] = q1; sD[2] = q2; sD[3] = q3; }
    }

    // ---- Step 3: dot products vs smem W ----
    float uA0 = 0.f, uA1 = 0.f, uA2 = 0.f, uA3 = 0.f;
    float uB0 = 0.f, uB1 = 0.f, uB2 = 0.f, uB3 = 0.f;
    #pragma unroll
    for (int k = 0; k < 8; k++) {
        const int i = k * 32 + lane;
        float4 w0 = sW[0][i];
        float4 w1 = sW[1][i];
        float4 w2 = sW[2][i];
        float4 w3 = sW[3][i];
        uA0 = dot4(xA[k], w0, uA0);  uB0 = dot4(xB[k], w0, uB0);
        uA1 = dot4(xA[k], w1, uA1);  uB1 = dot4(xB[k], w1, uB1);
        uA2 = dot4(xA[k], w2, uA2);  uB2 = dot4(xB[k], w2, uB2);
        uA3 = dot4(xA[k], w3, uA3);  uB3 = dot4(xB[k], w3, uB3);
    }

    #pragma unroll
    for (int o = 16; o; o >>= 1) {
        uA0 += __shfl_xor_sync(0xFFFFFFFFu, uA0, o);
        uA1 += __shfl_xor_sync(0xFFFFFFFFu, uA1, o);
        uA2 += __shfl_xor_sync(0xFFFFFFFFu, uA2, o);
        uA3 += __shfl_xor_sync(0xFFFFFFFFu, uA3, o);
        uB0 += __shfl_xor_sync(0xFFFFFFFFu, uB0, o);
        uB1 += __shfl_xor_sync(0xFFFFFFFFu, uB1, o);
        uB2 += __shfl_xor_sync(0xFFFFFFFFu, uB2, o);
        uB3 += __shfl_xor_sync(0xFFFFFFFFu, uB3, o);
    }

    __syncthreads();   // sD valid for everyone

    const float D1 = sD[1], D2 = sD[2], D3 = sD[3];

    float aA = 1.0f + uA0;                 // D0 == 0
    aA += fmaf(aA, uA1, D1);
    aA += fmaf(aA, uA2, D2);
    aA += fmaf(aA, uA3, D3);

    float aB = 1.0f + uB0;
    aB += fmaf(aB, uB1, D1);
    aB += fmaf(aB, uB2, D2);
    aB += fmaf(aB, uB3, D3);

    // ---- Step 4: out = a * x0 + Csum, streaming stores ----
    float4* __restrict__ oa = out + (size_t)rowA * DIM4;
    float4* __restrict__ ob = oa + DIM4;

    #pragma unroll
    for (int k = 0; k < 8; k++) {
        const int i = k * 32 + lane;
        float4 c = sC[i];
        float4 rA, rB;
        rA.x = fmaf(aA, xA[k].x, c.x); rA.y = fmaf(aA, xA[k].y, c.y);
        rA.z = fmaf(aA, xA[k].z, c.z); rA.w = fmaf(aA, xA[k].w, c.w);
        rB.x = fmaf(aB, xB[k].x, c.x); rB.y = fmaf(aB, xB[k].y, c.y);
        rB.z = fmaf(aB, xB[k].z, c.z); rB.w = fmaf(aB, xB[k].w, c.w);
        __stcs(&oa[i], rA);
        __stcs(&ob[i], rB);
    }
}

extern "C" void kernel_launch(void* const* d_in, const int* in_sizes, int n_in,
                              void* d_out, int out_size)
{
    const float* x0 = (const float*)d_in[0];   // [16384, 1024]
    const float* W  = (const float*)d_in[1];   // [4, 1024]
    const float* b  = (const float*)d_in[2];   // [4, 1024]
    float* out      = (float*)d_out;           // [16384, 1024]

    crossnet_fused<<<GRID, TPB>>>((const float4*)x0, (const float4*)W,
                                  (const float4*)b, (float4*)out);
}